// round 4
// baseline (speedup 1.0000x reference)
#include <cuda_runtime.h>
#include <cstdint>

#define BB 64
#define LL 4096
#define MM 256
#define AA 256
#define RR 512
#define NCHUNK 16   // L-splits for context partials

// -------- scratch (device globals: no allocation allowed) --------
__device__ float g_q[BB * AA];
__device__ float g_UaT[MM * AA];        // UaT[m][a] = Ua[a][m]
__device__ float g_e[BB * LL];
__device__ float g_attn[BB * LL];
__device__ float g_partial[BB * NCHUNK * MM];

// -------- packed f32x2 helpers (Blackwell FFMA2) --------
__device__ __forceinline__ unsigned long long dup2(float f) {
    unsigned int u = __float_as_uint(f);
    unsigned long long r;
    asm("mov.b64 %0, {%1, %2};" : "=l"(r) : "r"(u), "r"(u));
    return r;
}
__device__ __forceinline__ void ffma2(unsigned long long& d,
                                      unsigned long long a,
                                      unsigned long long b) {
    asm("fma.rn.f32x2 %0, %1, %2, %0;" : "+l"(d) : "l"(a), "l"(b));
}

// -------- kernel 1: transpose Ua [A,M] -> UaT [M,A] --------
__global__ void uat_kernel(const float* __restrict__ Ua) {
    __shared__ float tile[32][33];
    int m = blockIdx.x * 32 + threadIdx.x;
    int a = blockIdx.y * 32 + threadIdx.y;
    tile[threadIdx.y][threadIdx.x] = Ua[a * MM + m];
    __syncthreads();
    int ao = blockIdx.y * 32 + threadIdx.x;
    int mo = blockIdx.x * 32 + threadIdx.y;
    g_UaT[mo * AA + ao] = tile[threadIdx.x][threadIdx.y];
}

// -------- kernel 2: q[b][a] = hs[b] . Wa[a] + ba[a] --------
__global__ void q_kernel(const float* __restrict__ hs,
                         const float* __restrict__ Wa,
                         const float* __restrict__ ba) {
    __shared__ float h[RR];
    int b = blockIdx.x, t = threadIdx.x;
    h[t] = hs[b * RR + t];
    h[t + 256] = hs[b * RR + t + 256];
    __syncthreads();
    const float4* w4 = (const float4*)(Wa + (size_t)t * RR);
    float acc = 0.f;
#pragma unroll 8
    for (int r = 0; r < RR / 4; r++) {
        float4 v = w4[r];
        acc += v.x * h[4 * r] + v.y * h[4 * r + 1] + v.z * h[4 * r + 2] + v.w * h[4 * r + 3];
    }
    g_q[b * AA + t] = acc + ba[t];
}

// -------- kernel 3: scores  e[b][l] = w . tanh(q[b] + F[b,l] @ UaT) --------
// CTA: 64 L-rows x full A=256, K = M = 256 in chunks of 16, double-buffered.
// 256 threads = 8 warps. warp ty owns rows ty*8..+7; lane tx owns cols tx*8..+7
// as 4 f32x2 pairs. Inner: 32 FFMA2 per k (64 MACs).
__global__ __launch_bounds__(256, 2) void scores_kernel(const float* __restrict__ F,
                                                        const float* __restrict__ w) {
    const int b = blockIdx.y;
    const int l0 = blockIdx.x * 64;
    const int tid = threadIdx.x;
    const int tx = tid & 31;
    const int ty = tid >> 5;

    __shared__ float Fs[2][16][64];    // [k][l] transposed F tile
    __shared__ float Us[2][16][256];   // [k][a] from UaT

    const float* Fb = F + ((size_t)b * LL + l0) * MM;
    const int fl = tid >> 2;   // 0..63  (L row this thread loads)
    const int fj = tid & 3;    // 0..3   (float4 within 16-wide K chunk)

    unsigned long long acc[8][4];
#pragma unroll
    for (int r = 0; r < 8; r++)
#pragma unroll
        for (int c = 0; c < 4; c++) acc[r][c] = 0ULL;

    float4 fn;
    float4 un[4];

    // prefetch + store chunk 0
    fn = *(const float4*)(Fb + (size_t)fl * MM + 4 * fj);
#pragma unroll
    for (int i = 0; i < 4; i++) {
        int idx = tid + 256 * i;
        int k = idx >> 6, j = idx & 63;
        un[i] = ((const float4*)(g_UaT + (size_t)k * AA))[j];
    }
    Fs[0][4 * fj + 0][fl] = fn.x;
    Fs[0][4 * fj + 1][fl] = fn.y;
    Fs[0][4 * fj + 2][fl] = fn.z;
    Fs[0][4 * fj + 3][fl] = fn.w;
#pragma unroll
    for (int i = 0; i < 4; i++) {
        int idx = tid + 256 * i;
        int k = idx >> 6, j = idx & 63;
        ((float4*)Us[0][k])[j] = un[i];
    }
    __syncthreads();

    int s = 0;
    for (int kc = 0; kc < MM; kc += 16) {
        const bool more = (kc + 16) < MM;
        if (more) {
            fn = *(const float4*)(Fb + (size_t)fl * MM + kc + 16 + 4 * fj);
#pragma unroll
            for (int i = 0; i < 4; i++) {
                int idx = tid + 256 * i;
                int k = idx >> 6, j = idx & 63;
                un[i] = ((const float4*)(g_UaT + (size_t)(kc + 16 + k) * AA))[j];
            }
        }
#pragma unroll
        for (int k = 0; k < 16; k++) {
            float4 fa0 = *(const float4*)&Fs[s][k][ty * 8];
            float4 fa1 = *(const float4*)&Fs[s][k][ty * 8 + 4];
            ulonglong2 u01 = *(const ulonglong2*)&Us[s][k][tx * 8];
            ulonglong2 u23 = *(const ulonglong2*)&Us[s][k][tx * 8 + 4];
            unsigned long long d;
            d = dup2(fa0.x); ffma2(acc[0][0], d, u01.x); ffma2(acc[0][1], d, u01.y); ffma2(acc[0][2], d, u23.x); ffma2(acc[0][3], d, u23.y);
            d = dup2(fa0.y); ffma2(acc[1][0], d, u01.x); ffma2(acc[1][1], d, u01.y); ffma2(acc[1][2], d, u23.x); ffma2(acc[1][3], d, u23.y);
            d = dup2(fa0.z); ffma2(acc[2][0], d, u01.x); ffma2(acc[2][1], d, u01.y); ffma2(acc[2][2], d, u23.x); ffma2(acc[2][3], d, u23.y);
            d = dup2(fa0.w); ffma2(acc[3][0], d, u01.x); ffma2(acc[3][1], d, u01.y); ffma2(acc[3][2], d, u23.x); ffma2(acc[3][3], d, u23.y);
            d = dup2(fa1.x); ffma2(acc[4][0], d, u01.x); ffma2(acc[4][1], d, u01.y); ffma2(acc[4][2], d, u23.x); ffma2(acc[4][3], d, u23.y);
            d = dup2(fa1.y); ffma2(acc[5][0], d, u01.x); ffma2(acc[5][1], d, u01.y); ffma2(acc[5][2], d, u23.x); ffma2(acc[5][3], d, u23.y);
            d = dup2(fa1.z); ffma2(acc[6][0], d, u01.x); ffma2(acc[6][1], d, u01.y); ffma2(acc[6][2], d, u23.x); ffma2(acc[6][3], d, u23.y);
            d = dup2(fa1.w); ffma2(acc[7][0], d, u01.x); ffma2(acc[7][1], d, u01.y); ffma2(acc[7][2], d, u23.x); ffma2(acc[7][3], d, u23.y);
        }
        if (more) {
            Fs[s ^ 1][4 * fj + 0][fl] = fn.x;
            Fs[s ^ 1][4 * fj + 1][fl] = fn.y;
            Fs[s ^ 1][4 * fj + 2][fl] = fn.z;
            Fs[s ^ 1][4 * fj + 3][fl] = fn.w;
#pragma unroll
            for (int i = 0; i < 4; i++) {
                int idx = tid + 256 * i;
                int k = idx >> 6, j = idx & 63;
                ((float4*)Us[s ^ 1][k])[j] = un[i];
            }
        }
        __syncthreads();
        s ^= 1;
    }

    // epilogue: e_row = sum_a w[a] * tanh(q[a] + k[row][a]); warp-reduce over tx
    float qv[8], wv[8];
#pragma unroll
    for (int c = 0; c < 8; c++) {
        int a = tx * 8 + c;
        qv[c] = g_q[b * AA + a];
        wv[c] = w[a];
    }
#pragma unroll
    for (int r = 0; r < 8; r++) {
        float p = 0.f;
#pragma unroll
        for (int c = 0; c < 4; c++) {
            union { unsigned long long u; float2 f; } cv;
            cv.u = acc[r][c];
            p += wv[2 * c]     * tanhf(qv[2 * c]     + cv.f.x);
            p += wv[2 * c + 1] * tanhf(qv[2 * c + 1] + cv.f.y);
        }
#pragma unroll
        for (int o = 16; o > 0; o >>= 1) p += __shfl_xor_sync(0xffffffffu, p, o);
        if (tx == 0) g_e[b * LL + l0 + ty * 8 + r] = p;
    }
}

// -------- kernel 4: softmax over L per batch --------
__global__ void softmax_kernel() {
    const int b = blockIdx.x, t = threadIdx.x;
    __shared__ float red[256];
    float m = -1e30f;
    for (int l = t; l < LL; l += 256) m = fmaxf(m, g_e[b * LL + l]);
    red[t] = m;
    __syncthreads();
    for (int o = 128; o > 0; o >>= 1) {
        if (t < o) red[t] = fmaxf(red[t], red[t + o]);
        __syncthreads();
    }
    m = red[0];
    __syncthreads();
    float ssum = 0.f;
    for (int l = t; l < LL; l += 256) {
        float x = __expf(g_e[b * LL + l] - m);
        g_attn[b * LL + l] = x;
        ssum += x;
    }
    red[t] = ssum;
    __syncthreads();
    for (int o = 128; o > 0; o >>= 1) {
        if (t < o) red[t] += red[t + o];
        __syncthreads();
    }
    float inv = 1.f / red[0];
    for (int l = t; l < LL; l += 256) g_attn[b * LL + l] *= inv;
}

// -------- kernel 5: context partials over L chunks --------
__global__ void ctx_partial_kernel(const float* __restrict__ F) {
    const int b = blockIdx.y, ch = blockIdx.x;
    const int tid = threadIdx.x;
    const int g = tid >> 6;   // row group 0..3
    const int j = tid & 63;   // float4 column
    const int rows = LL / NCHUNK;  // 256
    const float* Fb = F + ((size_t)b * LL + (size_t)ch * rows) * MM;
    float4 acc = make_float4(0.f, 0.f, 0.f, 0.f);
    for (int i = 0; i < rows; i += 4) {
        int l = i + g;
        float a = g_attn[b * LL + ch * rows + l];
        float4 v = ((const float4*)(Fb + (size_t)l * MM))[j];
        acc.x += a * v.x; acc.y += a * v.y; acc.z += a * v.z; acc.w += a * v.w;
    }
    __shared__ float4 sr[256];
    sr[tid] = acc;
    __syncthreads();
    if (tid < 64) {
        float4 r0 = sr[tid], r1 = sr[tid + 64], r2 = sr[tid + 128], r3 = sr[tid + 192];
        float4 o;
        o.x = r0.x + r1.x + r2.x + r3.x;
        o.y = r0.y + r1.y + r2.y + r3.y;
        o.z = r0.z + r1.z + r2.z + r3.z;
        o.w = r0.w + r1.w + r2.w + r3.w;
        ((float4*)(g_partial + ((size_t)b * NCHUNK + ch) * MM))[tid] = o;
    }
}

// -------- kernel 6: reduce partials -> out [B, M] --------
__global__ void ctx_reduce_kernel(float* __restrict__ out) {
    int b = blockIdx.x, t = threadIdx.x;
    float s = 0.f;
#pragma unroll
    for (int ch = 0; ch < NCHUNK; ch++) s += g_partial[((size_t)b * NCHUNK + ch) * MM + t];
    out[b * MM + t] = s;
}

extern "C" void kernel_launch(void* const* d_in, const int* in_sizes, int n_in,
                              void* d_out, int out_size) {
    const float* hs = (const float*)d_in[0];
    const float* F  = (const float*)d_in[1];
    const float* Wa = (const float*)d_in[2];
    const float* Ua = (const float*)d_in[3];
    const float* w  = (const float*)d_in[4];
    const float* ba = (const float*)d_in[5];
    float* out = (float*)d_out;

    uat_kernel<<<dim3(8, 8), dim3(32, 32)>>>(Ua);
    q_kernel<<<BB, 256>>>(hs, Wa, ba);
    scores_kernel<<<dim3(LL / 64, BB), 256>>>(F, w);
    softmax_kernel<<<BB, 256>>>();
    ctx_partial_kernel<<<dim3(NCHUNK, BB), 256>>>(F);
    ctx_reduce_kernel<<<BB, 256>>>(out);
}

// round 6
// speedup vs baseline: 2.0764x; 2.0764x over previous
#include <cuda_runtime.h>
#include <cuda_bf16.h>
#include <cstdint>

#define BB 64
#define LL 4096
#define MM 256
#define AA 256
#define RR 512
#define NCHUNK 16

// -------- scratch (device globals: no allocation allowed) --------
__device__ float g_q[BB * AA];
__device__ float g_e[BB * LL];
__device__ float g_attn[BB * LL];
__device__ float g_partial[BB * NCHUNK * MM];
__device__ __nv_bfloat16 g_Uhi[AA * MM];   // [a][m] = [n][k] row-major
__device__ __nv_bfloat16 g_Ulo[AA * MM];

// ============ helpers ============
__device__ __forceinline__ uint32_t smem_u32(const void* p) {
    uint32_t a;
    asm("{ .reg .u64 t; cvta.to.shared.u64 t, %1; cvt.u32.u64 %0, t; }" : "=r"(a) : "l"(p));
    return a;
}
__device__ __forceinline__ void cvt_split(float x, unsigned short& h, unsigned short& l) {
    __nv_bfloat16 hb = __float2bfloat16_rn(x);
    float r = x - __bfloat162float(hb);
    __nv_bfloat16 lb = __float2bfloat16_rn(r);
    h = __bfloat16_as_ushort(hb);
    l = __bfloat16_as_ushort(lb);
}
__device__ __forceinline__ float tanh_fast(float x) {
    float y;
    asm("tanh.approx.f32 %0, %1;" : "=f"(y) : "f"(x));
    return y;
}
__device__ __forceinline__ void ldsm4(uint32_t r[4], uint32_t addr) {
    asm volatile("ldmatrix.sync.aligned.m8n8.x4.shared.b16 {%0,%1,%2,%3}, [%4];"
                 : "=r"(r[0]), "=r"(r[1]), "=r"(r[2]), "=r"(r[3]) : "r"(addr));
}
__device__ __forceinline__ void mma_bf16(float c[4], const uint32_t a[4],
                                         uint32_t b0, uint32_t b1) {
    asm volatile(
        "mma.sync.aligned.m16n8k16.row.col.f32.bf16.bf16.f32 "
        "{%0,%1,%2,%3}, {%4,%5,%6,%7}, {%8,%9}, {%0,%1,%2,%3};"
        : "+f"(c[0]), "+f"(c[1]), "+f"(c[2]), "+f"(c[3])
        : "r"(a[0]), "r"(a[1]), "r"(a[2]), "r"(a[3]), "r"(b0), "r"(b1));
}
#define CP_ASYNC16(dst, src) \
    asm volatile("cp.async.cg.shared.global [%0], [%1], 16;" :: "r"(dst), "l"(src) : "memory")
#define CP_COMMIT() asm volatile("cp.async.commit_group;" ::: "memory")
#define CP_WAIT0()  asm volatile("cp.async.wait_group 0;" ::: "memory")

// -------- kernel 0: split Ua -> bf16 hi/lo --------
__global__ void usplit_kernel(const float* __restrict__ Ua) {
    int i = blockIdx.x * 256 + threadIdx.x;
    float x = Ua[i];
    unsigned short h, l;
    cvt_split(x, h, l);
    g_Uhi[i] = __ushort_as_bfloat16(h);
    g_Ulo[i] = __ushort_as_bfloat16(l);
}

// -------- kernel 1: q[b][a] = hs[b] . Wa[a] + ba[a] --------
__global__ void q_kernel(const float* __restrict__ hs,
                         const float* __restrict__ Wa,
                         const float* __restrict__ ba) {
    __shared__ float h[RR];
    int b = blockIdx.x, t = threadIdx.x;
    h[t] = hs[b * RR + t];
    h[t + 256] = hs[b * RR + t + 256];
    __syncthreads();
    const float4* w4 = (const float4*)(Wa + (size_t)t * RR);
    float acc = 0.f;
#pragma unroll 8
    for (int r = 0; r < RR / 4; r++) {
        float4 v = w4[r];
        acc += v.x * h[4 * r] + v.y * h[4 * r + 1] + v.z * h[4 * r + 2] + v.w * h[4 * r + 3];
    }
    g_q[b * AA + t] = acc + ba[t];
}

// -------- kernel 2: scores via mma.sync bf16-split GEMM --------
// CTA: 128 L-rows x A=256, K=256 in 4 chunks of 64, double-buffered SMEM.
// 8 warps, 2(M) x 4(N) grid, warp tile 64x64, acc in registers (128 f32).
// SMEM rows padded to 144B (conflict-free ldmatrix without swizzle).
#define ROWB 144
#define FBUF 18432            // 128*144
#define UBUF 36864            // 256*144
#define SM_FHI 0
#define SM_FLO (2 * FBUF)
#define SM_UHI (4 * FBUF)
#define SM_ULO (SM_UHI + 2 * UBUF)
#define SM_QW  (SM_UHI + 4 * UBUF)
#define SM_TOTAL (SM_QW + 2048)

__global__ void __launch_bounds__(256, 1)
scores_kernel(const float* __restrict__ F, const float* __restrict__ w) {
    extern __shared__ char smem[];
    const uint32_t sb = smem_u32(smem);
    const int tid = threadIdx.x;
    const int lane = tid & 31;
    const int wid = tid >> 5;
    const int wm = wid >> 2;        // 0..1 : rows wm*64..+63
    const int wn = wid & 3;         // 0..3 : cols wn*64..+63
    const int b = blockIdx.y;
    const int l0 = blockIdx.x * 128;

    float* sq = (float*)(smem + SM_QW);
    float* swv = sq + 256;
    sq[tid] = g_q[b * AA + tid];
    swv[tid] = w[tid];

    const float* Fb = F + ((size_t)b * LL + l0) * MM;

    float acc[4][8][4];
#pragma unroll
    for (int mt = 0; mt < 4; mt++)
#pragma unroll
        for (int nt = 0; nt < 8; nt++)
#pragma unroll
            for (int j = 0; j < 4; j++) acc[mt][nt][j] = 0.f;

    float4 fr[8];

    // ---- prologue: chunk 0 ----
    {
        const int kc = 0;
#pragma unroll
        for (int s = 0; s < 8; s++) {   // U hi/lo via cp.async
            int lin = tid + 256 * s;
            int row = lin >> 3, c8 = lin & 7;
            uint32_t d = sb + SM_UHI + row * ROWB + c8 * 16;
            CP_ASYNC16(d, g_Uhi + (size_t)row * MM + kc + c8 * 8);
            uint32_t d2 = sb + SM_ULO + row * ROWB + c8 * 16;
            CP_ASYNC16(d2, g_Ulo + (size_t)row * MM + kc + c8 * 8);
        }
        CP_COMMIT();
#pragma unroll
        for (int s = 0; s < 8; s++) {
            int lin = tid + 256 * s;
            int row = lin >> 4, c4 = lin & 15;
            fr[s] = *(const float4*)(Fb + (size_t)row * MM + kc + c4 * 4);
        }
#pragma unroll
        for (int s = 0; s < 8; s++) {   // convert + store F chunk 0 to buf 0
            int lin = tid + 256 * s;
            int row = lin >> 4, c4 = lin & 15;
            unsigned short h0, q0, h1, q1, h2, q2, h3, q3;
            cvt_split(fr[s].x, h0, q0); cvt_split(fr[s].y, h1, q1);
            cvt_split(fr[s].z, h2, q2); cvt_split(fr[s].w, h3, q3);
            uint2 H, L;
            H.x = (uint32_t)h0 | ((uint32_t)h1 << 16);
            H.y = (uint32_t)h2 | ((uint32_t)h3 << 16);
            L.x = (uint32_t)q0 | ((uint32_t)q1 << 16);
            L.y = (uint32_t)q2 | ((uint32_t)q3 << 16);
            *(uint2*)(smem + SM_FHI + row * ROWB + c4 * 8) = H;
            *(uint2*)(smem + SM_FLO + row * ROWB + c4 * 8) = L;
        }
        CP_WAIT0();
        __syncthreads();
    }

    const uint32_t aoff = (uint32_t)((lane & 15) * ROWB + (lane >> 4) * 16);
    const uint32_t boff = (uint32_t)(((lane & 7) + ((lane >> 4) << 3)) * ROWB +
                                     (((lane >> 3) & 1) << 4));

    for (int p = 0; p < 4; p++) {
        const int buf = p & 1;
        const int nbuf = buf ^ 1;
        if (p < 3) {
            const int kc = (p + 1) * 64;
#pragma unroll
            for (int s = 0; s < 8; s++) {
                int lin = tid + 256 * s;
                int row = lin >> 3, c8 = lin & 7;
                uint32_t d = sb + SM_UHI + nbuf * UBUF + row * ROWB + c8 * 16;
                CP_ASYNC16(d, g_Uhi + (size_t)row * MM + kc + c8 * 8);
                uint32_t d2 = sb + SM_ULO + nbuf * UBUF + row * ROWB + c8 * 16;
                CP_ASYNC16(d2, g_Ulo + (size_t)row * MM + kc + c8 * 8);
            }
            CP_COMMIT();
#pragma unroll
            for (int s = 0; s < 8; s++) {
                int lin = tid + 256 * s;
                int row = lin >> 4, c4 = lin & 15;
                fr[s] = *(const float4*)(Fb + (size_t)row * MM + kc + c4 * 4);
            }
        }

        // ---- compute chunk p from buf ----
        {
            const uint32_t fhiB = sb + SM_FHI + buf * FBUF + wm * 64 * ROWB;
            const uint32_t floB = sb + SM_FLO + buf * FBUF + wm * 64 * ROWB;
            const uint32_t uhiB = sb + SM_UHI + buf * UBUF + wn * 64 * ROWB;
            const uint32_t uloB = sb + SM_ULO + buf * UBUF + wn * 64 * ROWB;
#pragma unroll
            for (int ks = 0; ks < 4; ks++) {
                uint32_t ah[4][4], bh[4][4];
#pragma unroll
                for (int mt = 0; mt < 4; mt++)
                    ldsm4(ah[mt], fhiB + mt * (16 * ROWB) + aoff + ks * 32);
#pragma unroll
                for (int np = 0; np < 4; np++)
                    ldsm4(bh[np], uhiB + np * (16 * ROWB) + boff + ks * 32);
#pragma unroll
                for (int mt = 0; mt < 4; mt++)
#pragma unroll
                    for (int np = 0; np < 4; np++) {
                        mma_bf16(acc[mt][2 * np],     ah[mt], bh[np][0], bh[np][1]);
                        mma_bf16(acc[mt][2 * np + 1], ah[mt], bh[np][2], bh[np][3]);
                    }
                uint32_t bl[4][4];
#pragma unroll
                for (int np = 0; np < 4; np++)
                    ldsm4(bl[np], uloB + np * (16 * ROWB) + boff + ks * 32);
#pragma unroll
                for (int mt = 0; mt < 4; mt++)
#pragma unroll
                    for (int np = 0; np < 4; np++) {
                        mma_bf16(acc[mt][2 * np],     ah[mt], bl[np][0], bl[np][1]);
                        mma_bf16(acc[mt][2 * np + 1], ah[mt], bl[np][2], bl[np][3]);
                    }
                uint32_t al[4][4];
#pragma unroll
                for (int mt = 0; mt < 4; mt++)
                    ldsm4(al[mt], floB + mt * (16 * ROWB) + aoff + ks * 32);
#pragma unroll
                for (int mt = 0; mt < 4; mt++)
#pragma unroll
                    for (int np = 0; np < 4; np++) {
                        mma_bf16(acc[mt][2 * np],     al[mt], bh[np][0], bh[np][1]);
                        mma_bf16(acc[mt][2 * np + 1], al[mt], bh[np][2], bh[np][3]);
                    }
            }
        }

        if (p < 3) {   // store next F chunk into nbuf; wait cp.async for U
#pragma unroll
            for (int s = 0; s < 8; s++) {
                int lin = tid + 256 * s;
                int row = lin >> 4, c4 = lin & 15;
                unsigned short h0, q0, h1, q1, h2, q2, h3, q3;
                cvt_split(fr[s].x, h0, q0); cvt_split(fr[s].y, h1, q1);
                cvt_split(fr[s].z, h2, q2); cvt_split(fr[s].w, h3, q3);
                uint2 H, L;
                H.x = (uint32_t)h0 | ((uint32_t)h1 << 16);
                H.y = (uint32_t)h2 | ((uint32_t)h3 << 16);
                L.x = (uint32_t)q0 | ((uint32_t)q1 << 16);
                L.y = (uint32_t)q2 | ((uint32_t)q3 << 16);
                *(uint2*)(smem + SM_FHI + nbuf * FBUF + row * ROWB + c4 * 8) = H;
                *(uint2*)(smem + SM_FLO + nbuf * FBUF + row * ROWB + c4 * 8) = L;
            }
            CP_WAIT0();
        }
        __syncthreads();
    }

    // ---- fused epilogue: e = sum_a w_a * tanh(q_a + k_a) ----
    float* epart = (float*)smem;   // 128 rows x 4 warp-columns (Fhi buf0 is free)
    const int g = lane >> 2;
    const int qr = lane & 3;
#pragma unroll
    for (int mt = 0; mt < 4; mt++) {
        float p0 = 0.f, p1 = 0.f;
#pragma unroll
        for (int nt = 0; nt < 8; nt++) {
#pragma unroll
            for (int j = 0; j < 2; j++) {
                int c = wn * 64 + nt * 8 + qr * 2 + j;
                float wc = swv[c], qc = sq[c];
                p0 += wc * tanh_fast(qc + acc[mt][nt][j]);
                p1 += wc * tanh_fast(qc + acc[mt][nt][2 + j]);
            }
        }
        p0 += __shfl_xor_sync(0xffffffffu, p0, 1);
        p0 += __shfl_xor_sync(0xffffffffu, p0, 2);
        p1 += __shfl_xor_sync(0xffffffffu, p1, 1);
        p1 += __shfl_xor_sync(0xffffffffu, p1, 2);
        if (qr == 0) {
            int r0 = wm * 64 + mt * 16 + g;
            epart[r0 * 4 + wn] = p0;
            epart[(r0 + 8) * 4 + wn] = p1;
        }
    }
    __syncthreads();
    if (tid < 128) {
        float e = epart[tid * 4] + epart[tid * 4 + 1] + epart[tid * 4 + 2] + epart[tid * 4 + 3];
        g_e[b * LL + l0 + tid] = e;
    }
}

// -------- kernel 3: softmax over L per batch --------
__global__ void softmax_kernel() {
    const int b = blockIdx.x, t = threadIdx.x;
    __shared__ float red[256];
    float m = -1e30f;
    for (int l = t; l < LL; l += 256) m = fmaxf(m, g_e[b * LL + l]);
    red[t] = m;
    __syncthreads();
    for (int o = 128; o > 0; o >>= 1) {
        if (t < o) red[t] = fmaxf(red[t], red[t + o]);
        __syncthreads();
    }
    m = red[0];
    __syncthreads();
    float ssum = 0.f;
    for (int l = t; l < LL; l += 256) {
        float x = __expf(g_e[b * LL + l] - m);
        g_attn[b * LL + l] = x;
        ssum += x;
    }
    red[t] = ssum;
    __syncthreads();
    for (int o = 128; o > 0; o >>= 1) {
        if (t < o) red[t] += red[t + o];
        __syncthreads();
    }
    float inv = 1.f / red[0];
    for (int l = t; l < LL; l += 256) g_attn[b * LL + l] *= inv;
}

// -------- kernel 4: context partials over L chunks --------
__global__ void ctx_partial_kernel(const float* __restrict__ F) {
    const int b = blockIdx.y, ch = blockIdx.x;
    const int tid = threadIdx.x;
    const int g = tid >> 6;
    const int j = tid & 63;
    const int rows = LL / NCHUNK;
    const float* Fb = F + ((size_t)b * LL + (size_t)ch * rows) * MM;
    float4 acc = make_float4(0.f, 0.f, 0.f, 0.f);
    for (int i = 0; i < rows; i += 4) {
        int l = i + g;
        float a = g_attn[b * LL + ch * rows + l];
        float4 v = ((const float4*)(Fb + (size_t)l * MM))[j];
        acc.x += a * v.x; acc.y += a * v.y; acc.z += a * v.z; acc.w += a * v.w;
    }
    __shared__ float4 sr[256];
    sr[tid] = acc;
    __syncthreads();
    if (tid < 64) {
        float4 r0 = sr[tid], r1 = sr[tid + 64], r2 = sr[tid + 128], r3 = sr[tid + 192];
        float4 o;
        o.x = r0.x + r1.x + r2.x + r3.x;
        o.y = r0.y + r1.y + r2.y + r3.y;
        o.z = r0.z + r1.z + r2.z + r3.z;
        o.w = r0.w + r1.w + r2.w + r3.w;
        ((float4*)(g_partial + ((size_t)b * NCHUNK + ch) * MM))[tid] = o;
    }
}

// -------- kernel 5: reduce partials -> out [B, M] --------
__global__ void ctx_reduce_kernel(float* __restrict__ out) {
    int b = blockIdx.x, t = threadIdx.x;
    float s = 0.f;
#pragma unroll
    for (int ch = 0; ch < NCHUNK; ch++) s += g_partial[((size_t)b * NCHUNK + ch) * MM + t];
    out[b * MM + t] = s;
}

extern "C" void kernel_launch(void* const* d_in, const int* in_sizes, int n_in,
                              void* d_out, int out_size) {
    const float* hs = (const float*)d_in[0];
    const float* F  = (const float*)d_in[1];
    const float* Wa = (const float*)d_in[2];
    const float* Ua = (const float*)d_in[3];
    const float* w  = (const float*)d_in[4];
    const float* ba = (const float*)d_in[5];
    float* out = (float*)d_out;

    static bool attr_done = false;
    if (!attr_done) {
        cudaFuncSetAttribute(scores_kernel,
                             cudaFuncAttributeMaxDynamicSharedMemorySize, SM_TOTAL);
        attr_done = true;
    }

    usplit_kernel<<<AA * MM / 256, 256>>>(Ua);
    q_kernel<<<BB, 256>>>(hs, Wa, ba);
    scores_kernel<<<dim3(LL / 128, BB), 256, SM_TOTAL>>>(F, w);
    softmax_kernel<<<BB, 256>>>();
    ctx_partial_kernel<<<dim3(NCHUNK, BB), 256>>>(F);
    ctx_reduce_kernel<<<BB, 256>>>(out);
}

// round 8
// speedup vs baseline: 2.1333x; 1.0274x over previous
#include <cuda_runtime.h>
#include <cuda_bf16.h>
#include <cstdint>

#define BB 64
#define LL 4096
#define MM 256
#define AA 256
#define RR 512
#define NTILE (LL / 128)          // 32 tiles per batch
#define NTOT  (BB * NTILE)        // 2048 tiles

// -------- scratch (device globals: no allocation allowed) --------
__device__ float g_q[BB * AA];
__device__ __nv_bfloat16 g_Uhi[AA * MM];   // [a][m] row-major (K-major)
__device__ __nv_bfloat16 g_Ulo[AA * MM];
__device__ float g_m[NTOT];
__device__ float g_s[NTOT];
__device__ float g_ctx[NTOT * MM];

// ============ helpers ============
__device__ __forceinline__ uint32_t smem_u32(const void* p) {
    uint32_t a;
    asm("{ .reg .u64 t; cvta.to.shared.u64 t, %1; cvt.u32.u64 %0, t; }" : "=r"(a) : "l"(p));
    return a;
}
__device__ __forceinline__ float tanh_fast(float x) {
    float y;
    asm("tanh.approx.f32 %0, %1;" : "=f"(y) : "f"(x));
    return y;
}
__device__ __forceinline__ void ldsm4(uint32_t r[4], uint32_t addr) {
    asm volatile("ldmatrix.sync.aligned.m8n8.x4.shared.b16 {%0,%1,%2,%3}, [%4];"
                 : "=r"(r[0]), "=r"(r[1]), "=r"(r[2]), "=r"(r[3]) : "r"(addr));
}
__device__ __forceinline__ void mma_bf16(float c[4], const uint32_t a[4],
                                         uint32_t b0, uint32_t b1) {
    asm volatile(
        "mma.sync.aligned.m16n8k16.row.col.f32.bf16.bf16.f32 "
        "{%0,%1,%2,%3}, {%4,%5,%6,%7}, {%8,%9}, {%0,%1,%2,%3};"
        : "+f"(c[0]), "+f"(c[1]), "+f"(c[2]), "+f"(c[3])
        : "r"(a[0]), "r"(a[1]), "r"(a[2]), "r"(a[3]), "r"(b0), "r"(b1));
}
#define CP_ASYNC16(dst, src) \
    asm volatile("cp.async.cg.shared.global [%0], [%1], 16;" :: "r"(dst), "l"(src) : "memory")
#define CP_COMMIT() asm volatile("cp.async.commit_group;" ::: "memory")
#define CP_WAIT0()  asm volatile("cp.async.wait_group 0;" ::: "memory")

// -------- kernel 0: split Ua -> bf16 hi/lo --------
__global__ void usplit_kernel(const float* __restrict__ Ua) {
    int i = blockIdx.x * 256 + threadIdx.x;
    float x = Ua[i];
    __nv_bfloat16 hb = __float2bfloat16_rn(x);
    float r = x - __bfloat162float(hb);
    g_Uhi[i] = hb;
    g_Ulo[i] = __float2bfloat16_rn(r);
}

// -------- kernel 1: q[b][a] = hs[b] . Wa[a] + ba[a] --------
__global__ void q_kernel(const float* __restrict__ hs,
                         const float* __restrict__ Wa,
                         const float* __restrict__ ba) {
    __shared__ float h[RR];
    int b = blockIdx.x, t = threadIdx.x;
    h[t] = hs[b * RR + t];
    h[t + 256] = hs[b * RR + t + 256];
    __syncthreads();
    const float4* w4 = (const float4*)(Wa + (size_t)t * RR);
    float acc = 0.f;
#pragma unroll 8
    for (int r = 0; r < RR / 4; r++) {
        float4 v = w4[r];
        acc += v.x * h[4 * r] + v.y * h[4 * r + 1] + v.z * h[4 * r + 2] + v.w * h[4 * r + 3];
    }
    g_q[b * AA + t] = acc + ba[t];
}

// -------- kernel 2: FUSED scores + local softmax + partial context --------
// Per CTA: 128 L-rows. F tile full-resident in SMEM as bf16 hi/lo (528B rows);
// U streamed in K=32 chunks, double-buffered (80B rows). 8 warps, 2x4, 64x64
// warp tiles, bf16 3-pass split GEMM, fused tanh/softmax/context epilogue.
#define KCH 32
#define NKCH 8
#define FROWB 528
#define UROWB 80
#define FSZ (128 * FROWB)          // 67584
#define USZ (AA * UROWB)           // 20480
#define SM_FHI 0
#define SM_FLO FSZ
#define SM_U   (2 * FSZ)                      // [buf][hi/lo] each USZ
#define SM_AUX (2 * FSZ + 4 * USZ)            // 217088
#define SM_TOTAL (SM_AUX + 4096)              // 221184

__global__ void __launch_bounds__(256, 1)
scores_kernel(const float* __restrict__ F, const float* __restrict__ w) {
    extern __shared__ char smem[];
    const uint32_t sb = smem_u32(smem);
    const int tid = threadIdx.x;
    const int lane = tid & 31;
    const int wid = tid >> 5;
    const int wm = wid >> 2;        // 0..1
    const int wn = wid & 3;         // 0..3
    const int b = blockIdx.y;
    const int tile = b * NTILE + blockIdx.x;
    const int l0 = blockIdx.x * 128;

    float* sq = (float*)(smem + SM_AUX);
    float* swv = sq + 256;
    sq[tid] = g_q[b * AA + tid];
    swv[tid] = w[tid];

    const float* Fb = F + ((size_t)b * LL + l0) * MM;

    float acc[4][8][4];
#pragma unroll
    for (int mt = 0; mt < 4; mt++)
#pragma unroll
        for (int nt = 0; nt < 8; nt++)
#pragma unroll
            for (int j = 0; j < 4; j++) acc[mt][nt][j] = 0.f;

    // F chunk staging: 4 float4 per thread (128x32 fp32 slice)
    const int frow = tid >> 3;        // wrong granularity? lin-based below
    (void)frow;
    float4 fr[4];

    // convert+store helper pattern (inlined twice)
#define CVT_STORE_F(KCBYTE)                                                    \
    do {                                                                       \
        _Pragma("unroll")                                                      \
        for (int s = 0; s < 4; s++) {                                          \
            int lin = tid + 256 * s;                                           \
            int row = lin >> 3, c4 = lin & 7;                                  \
            float4 v = fr[s];                                                  \
            __nv_bfloat162 h01 = __floats2bfloat162_rn(v.x, v.y);              \
            __nv_bfloat162 h23 = __floats2bfloat162_rn(v.z, v.w);              \
            float2 hf01 = __bfloat1622float2(h01);                             \
            float2 hf23 = __bfloat1622float2(h23);                             \
            __nv_bfloat162 l01 = __floats2bfloat162_rn(v.x - hf01.x, v.y - hf01.y); \
            __nv_bfloat162 l23 = __floats2bfloat162_rn(v.z - hf23.x, v.w - hf23.y); \
            uint2 H, L;                                                        \
            H.x = *(uint32_t*)&h01; H.y = *(uint32_t*)&h23;                    \
            L.x = *(uint32_t*)&l01; L.y = *(uint32_t*)&l23;                    \
            uint32_t off = row * FROWB + (KCBYTE) + c4 * 8;                    \
            *(uint2*)(smem + SM_FHI + off) = H;                                \
            *(uint2*)(smem + SM_FLO + off) = L;                                \
        }                                                                      \
    } while (0)

#define LOAD_F_REGS(KC)                                                        \
    do {                                                                       \
        _Pragma("unroll")                                                      \
        for (int s = 0; s < 4; s++) {                                          \
            int lin = tid + 256 * s;                                           \
            int row = lin >> 3, c4 = lin & 7;                                  \
            fr[s] = *(const float4*)(Fb + (size_t)row * MM + (KC) + c4 * 4);   \
        }                                                                      \
    } while (0)

#define LOAD_U_ASYNC(KC, BUF)                                                  \
    do {                                                                       \
        _Pragma("unroll")                                                      \
        for (int s = 0; s < 4; s++) {                                          \
            int lin = tid + 256 * s;                                           \
            int row = lin >> 2, c8 = lin & 3;                                  \
            uint32_t d = sb + SM_U + (BUF) * 2 * USZ + row * UROWB + c8 * 16;  \
            CP_ASYNC16(d, g_Uhi + (size_t)row * MM + (KC) + c8 * 8);           \
            CP_ASYNC16(d + USZ, g_Ulo + (size_t)row * MM + (KC) + c8 * 8);     \
        }                                                                      \
        CP_COMMIT();                                                           \
    } while (0)

    // ---- prologue: chunk 0 ----
    LOAD_U_ASYNC(0, 0);
    LOAD_F_REGS(0);
    CVT_STORE_F(0);
    CP_WAIT0();
    __syncthreads();

    const uint32_t aoff = (uint32_t)((lane & 15) * FROWB + (lane >> 4) * 16);
    const uint32_t boff = (uint32_t)(((lane & 7) + ((lane >> 4) << 3)) * UROWB +
                                     (((lane >> 3) & 1) << 4));
    const uint32_t fhiA = sb + SM_FHI + wm * 64 * FROWB + aoff;
    const uint32_t floA = sb + SM_FLO + wm * 64 * FROWB + aoff;

    for (int p = 0; p < NKCH; p++) {
        const int buf = p & 1;
        if (p < NKCH - 1) {
            LOAD_U_ASYNC((p + 1) * KCH, buf ^ 1);
            LOAD_F_REGS((p + 1) * KCH);
        }

        // ---- compute chunk p ----
        {
            const uint32_t kb = p * KCH * 2;   // byte offset in F rows
            const uint32_t uB = sb + SM_U + buf * 2 * USZ + wn * 64 * UROWB + boff;
#pragma unroll
            for (int ks = 0; ks < 2; ks++) {
                uint32_t ah[4][4], bh[4][4];
#pragma unroll
                for (int mt = 0; mt < 4; mt++)
                    ldsm4(ah[mt], fhiA + mt * (16 * FROWB) + kb + ks * 32);
#pragma unroll
                for (int np = 0; np < 4; np++)
                    ldsm4(bh[np], uB + np * (16 * UROWB) + ks * 32);
#pragma unroll
                for (int mt = 0; mt < 4; mt++)
#pragma unroll
                    for (int np = 0; np < 4; np++) {
                        mma_bf16(acc[mt][2 * np],     ah[mt], bh[np][0], bh[np][1]);
                        mma_bf16(acc[mt][2 * np + 1], ah[mt], bh[np][2], bh[np][3]);
                    }
                uint32_t bl[4][4];
#pragma unroll
                for (int np = 0; np < 4; np++)
                    ldsm4(bl[np], uB + USZ + np * (16 * UROWB) + ks * 32);
#pragma unroll
                for (int mt = 0; mt < 4; mt++)
#pragma unroll
                    for (int np = 0; np < 4; np++) {
                        mma_bf16(acc[mt][2 * np],     ah[mt], bl[np][0], bl[np][1]);
                        mma_bf16(acc[mt][2 * np + 1], ah[mt], bl[np][2], bl[np][3]);
                    }
                uint32_t al[4][4];
#pragma unroll
                for (int mt = 0; mt < 4; mt++)
                    ldsm4(al[mt], floA + mt * (16 * FROWB) + kb + ks * 32);
#pragma unroll
                for (int mt = 0; mt < 4; mt++)
#pragma unroll
                    for (int np = 0; np < 4; np++) {
                        mma_bf16(acc[mt][2 * np],     al[mt], bh[np][0], bh[np][1]);
                        mma_bf16(acc[mt][2 * np + 1], al[mt], bh[np][2], bh[np][3]);
                    }
            }
        }

        if (p < NKCH - 1) {
            CVT_STORE_F((p + 1) * KCH * 2);
            CP_WAIT0();
        }
        __syncthreads();
    }

    // ---- fused epilogue ----
    // 1) e_row = sum_a w_a * tanh(q_a + k_a), partials across 4 warp-columns
    float* epart = (float*)(smem + SM_U);       // 128 x 4
    const int g = lane >> 2;
    const int qr = lane & 3;
#pragma unroll
    for (int mt = 0; mt < 4; mt++) {
        float p0 = 0.f, p1 = 0.f;
#pragma unroll
        for (int nt = 0; nt < 8; nt++) {
#pragma unroll
            for (int j = 0; j < 2; j++) {
                int c = wn * 64 + nt * 8 + qr * 2 + j;
                float wc = swv[c], qc = sq[c];
                p0 += wc * tanh_fast(qc + acc[mt][nt][j]);
                p1 += wc * tanh_fast(qc + acc[mt][nt][2 + j]);
            }
        }
        p0 += __shfl_xor_sync(0xffffffffu, p0, 1);
        p0 += __shfl_xor_sync(0xffffffffu, p0, 2);
        p1 += __shfl_xor_sync(0xffffffffu, p1, 1);
        p1 += __shfl_xor_sync(0xffffffffu, p1, 2);
        if (qr == 0) {
            int r0 = wm * 64 + mt * 16 + g;
            epart[r0 * 4 + wn] = p0;
            epart[(r0 + 8) * 4 + wn] = p1;
        }
    }
    __syncthreads();

    float* es = (float*)(smem + SM_AUX + 2048);   // 128 floats
    float* sms = (float*)(smem + SM_AUX + 3072);  // scalars
    if (tid < 128)
        es[tid] = epart[tid * 4] + epart[tid * 4 + 1] + epart[tid * 4 + 2] + epart[tid * 4 + 3];
    __syncthreads();

    // 2) tile max
    if (tid < 32) {
        float m = fmaxf(fmaxf(es[tid], es[tid + 32]), fmaxf(es[tid + 64], es[tid + 96]));
#pragma unroll
        for (int o = 16; o > 0; o >>= 1) m = fmaxf(m, __shfl_xor_sync(0xffffffffu, m, o));
        if (tid == 0) sms[0] = m;
    }
    __syncthreads();
    float mt_val = sms[0];
    if (tid < 128) es[tid] = __expf(es[tid] - mt_val);   // es now holds p_l
    __syncthreads();

    // 3) tile sum + emit m_t, s_t
    if (tid < 32) {
        float s = es[tid] + es[tid + 32] + es[tid + 64] + es[tid + 96];
#pragma unroll
        for (int o = 16; o > 0; o >>= 1) s += __shfl_xor_sync(0xffffffffu, s, o);
        if (tid == 0) { g_m[tile] = mt_val; g_s[tile] = s; }
    }

    // 4) partial context: ctx[m] = sum_l p_l * (Fhi+Flo)[l][m]
    {
        const __nv_bfloat16* fh = (const __nv_bfloat16*)(smem + SM_FHI);
        const __nv_bfloat16* fl = (const __nv_bfloat16*)(smem + SM_FLO);
        const int stride = FROWB / 2;   // 264 bf16 per row
        float c0 = 0.f, c1 = 0.f;
#pragma unroll 4
        for (int l = 0; l < 128; l += 2) {
            float pl0 = es[l], pl1 = es[l + 1];
            float f0 = __bfloat162float(fh[l * stride + tid]) +
                       __bfloat162float(fl[l * stride + tid]);
            float f1 = __bfloat162float(fh[(l + 1) * stride + tid]) +
                       __bfloat162float(fl[(l + 1) * stride + tid]);
            c0 += pl0 * f0;
            c1 += pl1 * f1;
        }
        g_ctx[(size_t)tile * MM + tid] = c0 + c1;
    }
}

// -------- kernel 3: combine tiles per batch --------
__global__ void combine_kernel(float* __restrict__ out) {
    const int b = blockIdx.x, t = threadIdx.x;
    __shared__ float sc[NTILE];
    __shared__ float sS;
    if (t < NTILE) {
        float m = g_m[b * NTILE + t];
        float M = m;
#pragma unroll
        for (int o = 16; o > 0; o >>= 1) M = fmaxf(M, __shfl_xor_sync(0xffffffffu, M, o));
        float sc_t = __expf(m - M);
        sc[t] = sc_t;
        float s = g_s[b * NTILE + t] * sc_t;
#pragma unroll
        for (int o = 16; o > 0; o >>= 1) s += __shfl_xor_sync(0xffffffffu, s, o);
        if (t == 0) sS = s;
    }
    __syncthreads();
    float inv = 1.f / sS;
    float c = 0.f;
#pragma unroll
    for (int i = 0; i < NTILE; i++)
        c += sc[i] * g_ctx[(size_t)(b * NTILE + i) * MM + t];
    out[b * MM + t] = c * inv;
}

extern "C" void kernel_launch(void* const* d_in, const int* in_sizes, int n_in,
                              void* d_out, int out_size) {
    const float* hs = (const float*)d_in[0];
    const float* F  = (const float*)d_in[1];
    const float* Wa = (const float*)d_in[2];
    const float* Ua = (const float*)d_in[3];
    const float* w  = (const float*)d_in[4];
    const float* ba = (const float*)d_in[5];
    float* out = (float*)d_out;

    static bool attr_done = false;
    if (!attr_done) {
        cudaFuncSetAttribute(scores_kernel,
                             cudaFuncAttributeMaxDynamicSharedMemorySize, SM_TOTAL);
        attr_done = true;
    }

    usplit_kernel<<<AA * MM / 256, 256>>>(Ua);
    q_kernel<<<BB, 256>>>(hs, Wa, ba);
    scores_kernel<<<dim3(NTILE, BB), 256, SM_TOTAL>>>(F, w);
    combine_kernel<<<BB, 256>>>(out);
}

// round 13
// speedup vs baseline: 2.2750x; 1.0664x over previous
#include <cuda_runtime.h>
#include <cuda_bf16.h>
#include <cstdint>

#define BB 64
#define LL 4096
#define MM 256
#define AA 256
#define RR 512
#define NTILE (LL / 128)          // 32 tiles per batch
#define NTOT  (BB * NTILE)        // 2048 tiles

// -------- scratch (device globals: no allocation allowed) --------
__device__ float g_q[BB * AA];
__device__ __nv_bfloat16 g_Uhi[AA * MM];   // [a][m] row-major (K-major)
__device__ __nv_bfloat16 g_Ulo[AA * MM];
__device__ float g_m[NTOT];
__device__ float g_s[NTOT];
__device__ float g_ctx[NTOT * MM];

// ============ helpers ============
__device__ __forceinline__ uint32_t smem_u32(const void* p) {
    uint32_t a;
    asm("{ .reg .u64 t; cvta.to.shared.u64 t, %1; cvt.u32.u64 %0, t; }" : "=r"(a) : "l"(p));
    return a;
}
__device__ __forceinline__ float tanh_fast(float x) {
    float y;
    asm("tanh.approx.f32 %0, %1;" : "=f"(y) : "f"(x));
    return y;
}
__device__ __forceinline__ void ldsm4(uint32_t r[4], uint32_t addr) {
    asm volatile("ldmatrix.sync.aligned.m8n8.x4.shared.b16 {%0,%1,%2,%3}, [%4];"
                 : "=r"(r[0]), "=r"(r[1]), "=r"(r[2]), "=r"(r[3]) : "r"(addr));
}
__device__ __forceinline__ void mma_bf16(float c[4], const uint32_t a[4],
                                         uint32_t b0, uint32_t b1) {
    asm volatile(
        "mma.sync.aligned.m16n8k16.row.col.f32.bf16.bf16.f32 "
        "{%0,%1,%2,%3}, {%4,%5,%6,%7}, {%8,%9}, {%0,%1,%2,%3};"
        : "+f"(c[0]), "+f"(c[1]), "+f"(c[2]), "+f"(c[3])
        : "r"(a[0]), "r"(a[1]), "r"(a[2]), "r"(a[3]), "r"(b0), "r"(b1));
}
#define CP_ASYNC16(dst, src) \
    asm volatile("cp.async.cg.shared.global [%0], [%1], 16;" :: "r"(dst), "l"(src) : "memory")
#define CP_COMMIT() asm volatile("cp.async.commit_group;" ::: "memory")
#define CP_WAIT0()  asm volatile("cp.async.wait_group 0;" ::: "memory")

// -------- kernel 0: split Ua -> bf16 hi/lo --------
__global__ void usplit_kernel(const float* __restrict__ Ua) {
    int i = blockIdx.x * 256 + threadIdx.x;
    float x = Ua[i];
    __nv_bfloat16 hb = __float2bfloat16_rn(x);
    float r = x - __bfloat162float(hb);
    g_Uhi[i] = hb;
    g_Ulo[i] = __float2bfloat16_rn(r);
}

// -------- kernel 1: q[b][a] = hs[b] . Wa[a] + ba[a] --------
__global__ void q_kernel(const float* __restrict__ hs,
                         const float* __restrict__ Wa,
                         const float* __restrict__ ba) {
    __shared__ float h[RR];
    int b = blockIdx.x, t = threadIdx.x;
    h[t] = hs[b * RR + t];
    h[t + 256] = hs[b * RR + t + 256];
    __syncthreads();
    const float4* w4 = (const float4*)(Wa + (size_t)t * RR);
    float acc = 0.f;
#pragma unroll 8
    for (int r = 0; r < RR / 4; r++) {
        float4 v = w4[r];
        acc += v.x * h[4 * r] + v.y * h[4 * r + 1] + v.z * h[4 * r + 2] + v.w * h[4 * r + 3];
    }
    g_q[b * AA + t] = acc + ba[t];
}

// -------- kernel 2: FUSED scores + local softmax + partial context --------
// 512 threads, 16 warps in 4(M)x4(N); warp tile 32x64. F tile full-resident
// bf16 hi/lo (528B rows); U streamed in K=32 double-buffered chunks (80B rows).
#define KCH 32
#define NKCH 8
#define FROWB 528
#define UROWB 80
#define FSZ (128 * FROWB)          // 67584
#define USZ (AA * UROWB)           // 20480
#define SM_FHI 0
#define SM_FLO FSZ
#define SM_U   (2 * FSZ)                      // [buf][hi/lo] each USZ
#define SM_AUX (2 * FSZ + 4 * USZ)            // 217088
#define SM_TOTAL (SM_AUX + 4096)              // 221184

__global__ void __launch_bounds__(512, 1)
scores_kernel(const float* __restrict__ F, const float* __restrict__ w) {
    extern __shared__ char smem[];
    const uint32_t sb = smem_u32(smem);
    const int tid = threadIdx.x;
    const int lane = tid & 31;
    const int wid = tid >> 5;
    const int wm = wid >> 2;        // 0..3 : rows wm*32..+31
    const int wn = wid & 3;         // 0..3 : cols wn*64..+63
    const int b = blockIdx.y;
    const int tile = b * NTILE + blockIdx.x;
    const int l0 = blockIdx.x * 128;

    float* sq = (float*)(smem + SM_AUX);
    float* swv = sq + 256;
    if (tid < 256) {
        sq[tid] = g_q[b * AA + tid];
        swv[tid] = w[tid];
    }

    const float* Fb = F + ((size_t)b * LL + l0) * MM;

    float acc[2][8][4];
#pragma unroll
    for (int mt = 0; mt < 2; mt++)
#pragma unroll
        for (int nt = 0; nt < 8; nt++)
#pragma unroll
            for (int j = 0; j < 4; j++) acc[mt][nt][j] = 0.f;

    float4 fr[2];

#define LOAD_F_REGS(KC)                                                        \
    do {                                                                       \
        _Pragma("unroll")                                                      \
        for (int s = 0; s < 2; s++) {                                          \
            int lin = tid + 512 * s;                                           \
            int row = lin >> 3, c4 = lin & 7;                                  \
            fr[s] = *(const float4*)(Fb + (size_t)row * MM + (KC) + c4 * 4);   \
        }                                                                      \
    } while (0)

#define CVT_STORE_F(KCBYTE)                                                    \
    do {                                                                       \
        _Pragma("unroll")                                                      \
        for (int s = 0; s < 2; s++) {                                          \
            int lin = tid + 512 * s;                                           \
            int row = lin >> 3, c4 = lin & 7;                                  \
            float4 v = fr[s];                                                  \
            __nv_bfloat162 h01 = __floats2bfloat162_rn(v.x, v.y);              \
            __nv_bfloat162 h23 = __floats2bfloat162_rn(v.z, v.w);              \
            float2 hf01 = __bfloat1622float2(h01);                             \
            float2 hf23 = __bfloat1622float2(h23);                             \
            __nv_bfloat162 l01 = __floats2bfloat162_rn(v.x - hf01.x, v.y - hf01.y); \
            __nv_bfloat162 l23 = __floats2bfloat162_rn(v.z - hf23.x, v.w - hf23.y); \
            uint2 H, L;                                                        \
            H.x = *(uint32_t*)&h01; H.y = *(uint32_t*)&h23;                    \
            L.x = *(uint32_t*)&l01; L.y = *(uint32_t*)&l23;                    \
            uint32_t off = row * FROWB + (KCBYTE) + c4 * 8;                    \
            *(uint2*)(smem + SM_FHI + off) = H;                                \
            *(uint2*)(smem + SM_FLO + off) = L;                                \
        }                                                                      \
    } while (0)

#define LOAD_U_ASYNC(KC, BUF)                                                  \
    do {                                                                       \
        _Pragma("unroll")                                                      \
        for (int s = 0; s < 2; s++) {                                          \
            int lin = tid + 512 * s;                                           \
            int row = lin >> 2, c8 = lin & 3;                                  \
            uint32_t d = sb + SM_U + (BUF) * 2 * USZ + row * UROWB + c8 * 16;  \
            CP_ASYNC16(d, g_Uhi + (size_t)row * MM + (KC) + c8 * 8);           \
            CP_ASYNC16(d + USZ, g_Ulo + (size_t)row * MM + (KC) + c8 * 8);     \
        }                                                                      \
        CP_COMMIT();                                                           \
    } while (0)

    // ---- prologue: chunk 0 ----
    LOAD_U_ASYNC(0, 0);
    LOAD_F_REGS(0);
    CVT_STORE_F(0);
    CP_WAIT0();
    __syncthreads();

    const uint32_t aoff = (uint32_t)((lane & 15) * FROWB + (lane >> 4) * 16);
    const uint32_t boff = (uint32_t)(((lane & 7) + ((lane >> 4) << 3)) * UROWB +
                                     (((lane >> 3) & 1) << 4));
    const uint32_t fhiA = sb + SM_FHI + wm * 32 * FROWB + aoff;
    const uint32_t floA = sb + SM_FLO + wm * 32 * FROWB + aoff;

    for (int p = 0; p < NKCH; p++) {
        const int buf = p & 1;
        if (p < NKCH - 1) {
            LOAD_U_ASYNC((p + 1) * KCH, buf ^ 1);
            LOAD_F_REGS((p + 1) * KCH);
        }

        // ---- compute chunk p ----
        {
            const uint32_t kb = p * KCH * 2;   // byte offset into F rows
            const uint32_t uB = sb + SM_U + buf * 2 * USZ + wn * 64 * UROWB + boff;
#pragma unroll
            for (int ks = 0; ks < 2; ks++) {
                uint32_t ah[2][4], al[2][4];
#pragma unroll
                for (int mt = 0; mt < 2; mt++) {
                    ldsm4(ah[mt], fhiA + mt * (16 * FROWB) + kb + ks * 32);
                    ldsm4(al[mt], floA + mt * (16 * FROWB) + kb + ks * 32);
                }
#pragma unroll
                for (int half = 0; half < 2; half++) {
                    uint32_t bh[2][4], bl[2][4];
#pragma unroll
                    for (int np = 0; np < 2; np++) {
                        ldsm4(bh[np], uB + (half * 2 + np) * (16 * UROWB) + ks * 32);
                        ldsm4(bl[np], uB + USZ + (half * 2 + np) * (16 * UROWB) + ks * 32);
                    }
                    // pass 1: hi * hi
#pragma unroll
                    for (int mt = 0; mt < 2; mt++)
#pragma unroll
                        for (int np = 0; np < 2; np++) {
                            int nt = 2 * (2 * half + np);
                            mma_bf16(acc[mt][nt],     ah[mt], bh[np][0], bh[np][1]);
                            mma_bf16(acc[mt][nt + 1], ah[mt], bh[np][2], bh[np][3]);
                        }
                    // pass 2: hi * lo
#pragma unroll
                    for (int mt = 0; mt < 2; mt++)
#pragma unroll
                        for (int np = 0; np < 2; np++) {
                            int nt = 2 * (2 * half + np);
                            mma_bf16(acc[mt][nt],     ah[mt], bl[np][0], bl[np][1]);
                            mma_bf16(acc[mt][nt + 1], ah[mt], bl[np][2], bl[np][3]);
                        }
                    // pass 3: lo * hi
#pragma unroll
                    for (int mt = 0; mt < 2; mt++)
#pragma unroll
                        for (int np = 0; np < 2; np++) {
                            int nt = 2 * (2 * half + np);
                            mma_bf16(acc[mt][nt],     al[mt], bh[np][0], bh[np][1]);
                            mma_bf16(acc[mt][nt + 1], al[mt], bh[np][2], bh[np][3]);
                        }
                }
            }
        }

        if (p < NKCH - 1) {
            CVT_STORE_F((p + 1) * KCH * 2);
            CP_WAIT0();
        }
        __syncthreads();
    }

    // ---- fused epilogue ----
    // 1) e partials: each warp covers rows wm*32+mt*16+{g,g+8}, cols wn*64..+63
    float* epart = (float*)(smem + SM_U);       // 128 x 4 floats
    const int g = lane >> 2;
    const int qr = lane & 3;
#pragma unroll
    for (int mt = 0; mt < 2; mt++) {
        float p0 = 0.f, p1 = 0.f;
#pragma unroll
        for (int nt = 0; nt < 8; nt++) {
#pragma unroll
            for (int j = 0; j < 2; j++) {
                int c = wn * 64 + nt * 8 + qr * 2 + j;
                float wc = swv[c], qc = sq[c];
                p0 += wc * tanh_fast(qc + acc[mt][nt][j]);
                p1 += wc * tanh_fast(qc + acc[mt][nt][2 + j]);
            }
        }
        p0 += __shfl_xor_sync(0xffffffffu, p0, 1);
        p0 += __shfl_xor_sync(0xffffffffu, p0, 2);
        p1 += __shfl_xor_sync(0xffffffffu, p1, 1);
        p1 += __shfl_xor_sync(0xffffffffu, p1, 2);
        if (qr == 0) {
            int r0 = wm * 32 + mt * 16 + g;
            epart[r0 * 4 + wn] = p0;
            epart[(r0 + 8) * 4 + wn] = p1;
        }
    }
    __syncthreads();

    float* es = (float*)(smem + SM_AUX + 2048);   // 128 floats
    float* sms = (float*)(smem + SM_AUX + 3072);  // scalars
    if (tid < 128)
        es[tid] = epart[tid * 4] + epart[tid * 4 + 1] + epart[tid * 4 + 2] + epart[tid * 4 + 3];
    __syncthreads();

    // 2) tile max
    if (tid < 32) {
        float m = fmaxf(fmaxf(es[tid], es[tid + 32]), fmaxf(es[tid + 64], es[tid + 96]));
#pragma unroll
        for (int o = 16; o > 0; o >>= 1) m = fmaxf(m, __shfl_xor_sync(0xffffffffu, m, o));
        if (tid == 0) sms[0] = m;
    }
    __syncthreads();
    float mt_val = sms[0];
    if (tid < 128) es[tid] = __expf(es[tid] - mt_val);   // es now holds p_l
    __syncthreads();

    // 3) tile sum + emit m_t, s_t
    if (tid < 32) {
        float s = es[tid] + es[tid + 32] + es[tid + 64] + es[tid + 96];
#pragma unroll
        for (int o = 16; o > 0; o >>= 1) s += __shfl_xor_sync(0xffffffffu, s, o);
        if (tid == 0) { g_m[tile] = mt_val; g_s[tile] = s; }
    }

    // 4) partial context, vectorized across 512 threads:
    //    thread handles column-pair (tid&127), row quarter (tid>>7)
    {
        const int c2 = tid & 127;
        const int rh = tid >> 7;           // 0..3
        const __nv_bfloat162* fh2 = (const __nv_bfloat162*)(smem + SM_FHI);
        const __nv_bfloat162* fl2 = (const __nv_bfloat162*)(smem + SM_FLO);
        const int stride2 = FROWB / 4;     // 132 bf162 per row
        float2 cacc = make_float2(0.f, 0.f);
#pragma unroll 8
        for (int i = 0; i < 32; i++) {
            int l = rh * 32 + i;
            float pl = es[l];
            float2 hf = __bfloat1622float2(fh2[l * stride2 + c2]);
            float2 lf = __bfloat1622float2(fl2[l * stride2 + c2]);
            cacc.x += pl * (hf.x + lf.x);
            cacc.y += pl * (hf.y + lf.y);
        }
        float2* cbuf = (float2*)(smem + SM_U + 4096);
        cbuf[rh * 128 + c2] = cacc;
    }
    __syncthreads();
    if (tid < 128) {
        float2* cbuf = (float2*)(smem + SM_U + 4096);
        float2 a0 = cbuf[tid], a1 = cbuf[128 + tid], a2 = cbuf[256 + tid], a3 = cbuf[384 + tid];
        float2 o;
        o.x = a0.x + a1.x + a2.x + a3.x;
        o.y = a0.y + a1.y + a2.y + a3.y;
        *(float2*)(g_ctx + (size_t)tile * MM + 2 * tid) = o;
    }
}

// -------- kernel 3: combine tiles per batch --------
__global__ void combine_kernel(float* __restrict__ out) {
    const int b = blockIdx.x, t = threadIdx.x;
    __shared__ float sc[NTILE];
    __shared__ float sS;
    if (t < NTILE) {
        float m = g_m[b * NTILE + t];
        float M = m;
#pragma unroll
        for (int o = 16; o > 0; o >>= 1) M = fmaxf(M, __shfl_xor_sync(0xffffffffu, M, o));
        float sc_t = __expf(m - M);
        sc[t] = sc_t;
        float s = g_s[b * NTILE + t] * sc_t;
#pragma unroll
        for (int o = 16; o > 0; o >>= 1) s += __shfl_xor_sync(0xffffffffu, s, o);
        if (t == 0) sS = s;
    }
    __syncthreads();
    float inv = 1.f / sS;
    float c = 0.f;
#pragma unroll
    for (int i = 0; i < NTILE; i++)
        c += sc[i] * g_ctx[(size_t)(b * NTILE + i) * MM + t];
    out[b * MM + t] = c * inv;
}

extern "C" void kernel_launch(void* const* d_in, const int* in_sizes, int n_in,
                              void* d_out, int out_size) {
    const float* hs = (const float*)d_in[0];
    const float* F  = (const float*)d_in[1];
    const float* Wa = (const float*)d_in[2];
    const float* Ua = (const float*)d_in[3];
    const float* w  = (const float*)d_in[4];
    const float* ba = (const float*)d_in[5];
    float* out = (float*)d_out;

    static bool attr_done = false;
    if (!attr_done) {
        cudaFuncSetAttribute(scores_kernel,
                             cudaFuncAttributeMaxDynamicSharedMemorySize, SM_TOTAL);
        attr_done = true;
    }

    usplit_kernel<<<AA * MM / 256, 256>>>(Ua);
    q_kernel<<<BB, 256>>>(hs, Wa, ba);
    scores_kernel<<<dim3(NTILE, BB), 512, SM_TOTAL>>>(F, w);
    combine_kernel<<<BB, 256>>>(out);
}